// round 10
// baseline (speedup 1.0000x reference)
#include <cuda_runtime.h>

#define NPTS   16384
#define NBATCH 2
#define NSEED  1024
#define NDEPTH 4
#define NSAMP  64
#define NGRP   (NBATCH*NSEED*NDEPTH)   // 8192
#define OUTSZ  (NBATCH*256*NSEED*NDEPTH)

// ---------------- scratch (__device__ globals; no allocation allowed) -------
__device__ float    g_px[NBATCH][NPTS];
__device__ float    g_py[NBATCH][NPTS];
__device__ float    g_pz[NBATCH][NPTS];
__device__ float    g_groups[NGRP * 192];       // [g][c(3)][slot(64)]
__device__ unsigned g_wl[NGRP * NSAMP];         // worklist: g*64+slot
__device__ int      g_total;
__device__ float    g_w1f[192],   g_b1f[64];
__device__ float    g_w2f[8192],  g_b2f[128];
__device__ float    g_w3f[32768], g_b3f[256];

// ---------------- kernel 0: fold BN into weights, SoA transpose, zero out ---
__global__ void prep_kernel(
    const float* __restrict__ pc,
    const float* __restrict__ w1, const float* __restrict__ b1, const float* __restrict__ ga1,
    const float* __restrict__ be1, const float* __restrict__ m1, const float* __restrict__ v1,
    const float* __restrict__ w2, const float* __restrict__ b2, const float* __restrict__ ga2,
    const float* __restrict__ be2, const float* __restrict__ m2, const float* __restrict__ v2,
    const float* __restrict__ w3, const float* __restrict__ b3, const float* __restrict__ ga3,
    const float* __restrict__ be3, const float* __restrict__ m3, const float* __restrict__ v3,
    float* __restrict__ out)
{
    int tid = blockIdx.x * blockDim.x + threadIdx.x;
    int stride = gridDim.x * blockDim.x;
    for (int i = tid; i < 192; i += stride)   { int o = i / 3;  g_w1f[i] = w1[i] * (ga1[o] * rsqrtf(v1[o] + 1e-5f)); }
    for (int i = tid; i < 64; i += stride)    { float s = ga1[i] * rsqrtf(v1[i] + 1e-5f); g_b1f[i] = (b1[i] - m1[i]) * s + be1[i]; }
    for (int i = tid; i < 8192; i += stride)  { int o = i >> 6; g_w2f[i] = w2[i] * (ga2[o] * rsqrtf(v2[o] + 1e-5f)); }
    for (int i = tid; i < 128; i += stride)   { float s = ga2[i] * rsqrtf(v2[i] + 1e-5f); g_b2f[i] = (b2[i] - m2[i]) * s + be2[i]; }
    for (int i = tid; i < 32768; i += stride) { int o = i >> 7; g_w3f[i] = w3[i] * (ga3[o] * rsqrtf(v3[o] + 1e-5f)); }
    for (int i = tid; i < 256; i += stride)   { float s = ga3[i] * rsqrtf(v3[i] + 1e-5f); g_b3f[i] = (b3[i] - m3[i]) * s + be3[i]; }
    for (int i = tid; i < NBATCH * NPTS; i += stride) {
        int b = i >> 14, n = i & (NPTS - 1);
        const float* p = pc + (size_t)i * 3;
        g_px[b][n] = p[0]; g_py[b][n] = p[1]; g_pz[b][n] = p[2];
    }
    for (int i = tid; i < OUTSZ; i += stride) out[i] = 0.0f;
    if (tid == 0) g_total = 0;
}

// ---------------- kernel 1: warp-per-seed ordered cylinder selection --------
__global__ void __launch_bounds__(256) group_kernel(
    const float* __restrict__ seed_xyz, const float* __restrict__ vp_rot)
{
    int warp = blockIdx.x * 8 + (threadIdx.x >> 5);   // 0..2047 = b*1024+s
    int lane = threadIdx.x & 31;
    int b = warp >> 10;

    const float* sp = seed_xyz + (size_t)warp * 3;
    float sx = sp[0], sy = sp[1], sz = sp[2];
    const float* R = vp_rot + (size_t)warp * 9;        // R[c][d]
    float r00 = R[0], r01 = R[1], r02 = R[2];
    float r10 = R[3], r11 = R[4], r12 = R[5];
    float r20 = R[6], r21 = R[7], r22 = R[8];

    const float* __restrict__ px = g_px[b];
    const float* __restrict__ py = g_py[b];
    const float* __restrict__ pz = g_pz[b];

    int c0 = 0, c1 = 0, c2 = 0, c3 = 0;
    unsigned lm = (1u << lane) - 1u;
    float* gb = g_groups + (size_t)warp * (4 * 192);

    for (int n0 = 0; n0 < NPTS; n0 += 32) {
        int n = n0 + lane;
        float dx = px[n] - sx, dy = py[n] - sy, dz = pz[n] - sz;
        float h  = dx * r00 + dy * r10 + dz * r20;
        float yy = dx * r01 + dy * r11 + dz * r21;
        float zz = dx * r02 + dy * r12 + dz * r22;
        bool bs = (yy * yy + zz * zz < 0.0025f) && (h > -0.02f);
        unsigned bal; bool m;
        m = bs && (h < 0.01f); bal = __ballot_sync(0xffffffffu, m);
        if (bal) { int slot = c0 + __popc(bal & lm); if (m && slot < 64) { float* o = gb + slot;       o[0] = h; o[64] = yy; o[128] = zz; } c0 += __popc(bal); }
        m = bs && (h < 0.02f); bal = __ballot_sync(0xffffffffu, m);
        if (bal) { int slot = c1 + __popc(bal & lm); if (m && slot < 64) { float* o = gb + 192 + slot; o[0] = h; o[64] = yy; o[128] = zz; } c1 += __popc(bal); }
        m = bs && (h < 0.03f); bal = __ballot_sync(0xffffffffu, m);
        if (bal) { int slot = c2 + __popc(bal & lm); if (m && slot < 64) { float* o = gb + 384 + slot; o[0] = h; o[64] = yy; o[128] = zz; } c2 += __popc(bal); }
        m = bs && (h < 0.04f); bal = __ballot_sync(0xffffffffu, m);
        if (bal) { int slot = c3 + __popc(bal & lm); if (m && slot < 64) { float* o = gb + 576 + slot; o[0] = h; o[64] = yy; o[128] = zz; } c3 += __popc(bal); }
        if (c0 >= 64) break;   // masks nested: c0 <= c1 <= c2 <= c3
    }

    // fallback value = d_rot of point 0 (reference pads with index 0 if empty)
    float fdx = px[0] - sx, fdy = py[0] - sy, fdz = pz[0] - sz;
    float h0 = fdx * r00 + fdy * r10 + fdz * r20;
    float y0 = fdx * r01 + fdy * r11 + fdz * r21;
    float z0 = fdx * r02 + fdy * r12 + fdz * r22;

    int cnt[4] = {c0, c1, c2, c3};
    int eff[4], tot = 0;
#pragma unroll
    for (int d = 0; d < 4; d++) {
        int e = cnt[d] < 64 ? cnt[d] : 64;
        if (e == 0) {
            if (lane == 0) { float* o = gb + d * 192; o[0] = h0; o[64] = y0; o[128] = z0; }
            e = 1;   // padding duplicates first value; max over dupes == single sample
        }
        eff[d] = e; tot += e;
    }
    int base = 0;
    if (lane == 0) base = atomicAdd(&g_total, tot);
    base = __shfl_sync(0xffffffffu, base, 0);
#pragma unroll
    for (int d = 0; d < 4; d++) {
        unsigned gid = (unsigned)(warp * 4 + d) * 64u;
        for (int sl = lane; sl < eff[d]; sl += 32) g_wl[base + sl] = gid + (unsigned)sl;
        base += eff[d];
    }
}

// ---------------- kernel 2: persistent fused MLP over the sample worklist ---
#define SMEM2_FLOATS (8192 + 32768 + 192 + 64 + 128 + 256 + 192 + 4096 + 8192 + 64)
#define SMEM2_BYTES  (SMEM2_FLOATS * 4)

#define ACC8(A, wc, p, q)                                              \
    (A)[0] += (wc) * (p).x; (A)[1] += (wc) * (p).y;                    \
    (A)[2] += (wc) * (p).z; (A)[3] += (wc) * (p).w;                    \
    (A)[4] += (wc) * (q).x; (A)[5] += (wc) * (q).y;                    \
    (A)[6] += (wc) * (q).z; (A)[7] += (wc) * (q).w;

__global__ void __launch_bounds__(256, 1) mlp_kernel(float* __restrict__ out)
{
    extern __shared__ float sm[];
    float* sW2 = sm;                 // 8192
    float* sW3 = sW2 + 8192;         // 32768
    float* sW1 = sW3 + 32768;        // 192
    float* sB1 = sW1 + 192;          // 64
    float* sB2 = sB1 + 64;           // 128
    float* sB3 = sB2 + 128;          // 256
    float* sX  = sB3 + 256;          // 192  (3 x 64)
    float* sH1 = sX + 192;           // 4096 (64 x 64)
    float* sH2 = sH1 + 4096;         // 8192 (128 x 64)
    int*   sOB = (int*)(sH2 + 8192); // 64

    int tid = threadIdx.x;
    for (int i = tid; i < 8192; i += 256)  sW2[i] = g_w2f[i];
    for (int i = tid; i < 32768; i += 256) sW3[i] = g_w3f[i];
    if (tid < 192) sW1[tid] = g_w1f[tid];
    if (tid < 64)  sB1[tid] = g_b1f[tid];
    if (tid < 128) sB2[tid] = g_b2f[tid];
    sB3[tid] = g_b3f[tid];

    int total = g_total;
    int nb = (total + 63) >> 6;

    for (int bt = blockIdx.x; bt < nb; bt += gridDim.x) {
        __syncthreads();
        if (tid < 64) {
            int k = bt * 64 + tid;
            if (k < total) {
                unsigned e = g_wl[k];
                unsigned g4 = e >> 6, slot = e & 63u;
                const float* s = g_groups + (size_t)g4 * 192 + slot;
                sX[tid] = s[0]; sX[64 + tid] = s[64]; sX[128 + tid] = s[128];
                int bb = (int)(g4 >> 12), ss = (int)((g4 >> 2) & 1023), dd = (int)(g4 & 3);
                sOB[tid] = bb * 1048576 + ss * 4 + dd;   // + o*4096 later
            } else {
                sX[tid] = 0.f; sX[64 + tid] = 0.f; sX[128 + tid] = 0.f; sOB[tid] = -1;
            }
        }
        __syncthreads();

        // ---- layer 1: 3 -> 64 ----
        {
            int o = tid >> 2, k0 = (tid & 3) << 4;
            float w0 = sW1[o * 3], w1 = sW1[o * 3 + 1], w2 = sW1[o * 3 + 2], bb = sB1[o];
#pragma unroll
            for (int j = 0; j < 16; j++) {
                int k = k0 + j;
                float v = bb + w0 * sX[k] + w1 * sX[64 + k] + w2 * sX[128 + k];
                sH1[o * 64 + k] = fmaxf(v, 0.f);
            }
        }
        __syncthreads();

        // ---- layer 2: 64 -> 128 (4 o x 8 k per thread) ----
        {
            int to = (tid >> 3) << 2, k0 = (tid & 7) << 3;
            float acc[4][8];
#pragma unroll
            for (int i = 0; i < 4; i++)
#pragma unroll
                for (int j = 0; j < 8; j++) acc[i][j] = 0.f;
#pragma unroll 4
            for (int c4 = 0; c4 < 16; c4++) {
                int c = c4 << 2;
                float4 a0 = *(const float4*)&sH1[(c + 0) * 64 + k0];
                float4 q0 = *(const float4*)&sH1[(c + 0) * 64 + k0 + 4];
                float4 a1 = *(const float4*)&sH1[(c + 1) * 64 + k0];
                float4 q1 = *(const float4*)&sH1[(c + 1) * 64 + k0 + 4];
                float4 a2 = *(const float4*)&sH1[(c + 2) * 64 + k0];
                float4 q2 = *(const float4*)&sH1[(c + 2) * 64 + k0 + 4];
                float4 a3 = *(const float4*)&sH1[(c + 3) * 64 + k0];
                float4 q3 = *(const float4*)&sH1[(c + 3) * 64 + k0 + 4];
#pragma unroll
                for (int i = 0; i < 4; i++) {
                    float4 w = *(const float4*)&sW2[(to + i) * 64 + c];
                    ACC8(acc[i], w.x, a0, q0)
                    ACC8(acc[i], w.y, a1, q1)
                    ACC8(acc[i], w.z, a2, q2)
                    ACC8(acc[i], w.w, a3, q3)
                }
            }
#pragma unroll
            for (int i = 0; i < 4; i++) {
                float bb = sB2[to + i];
#pragma unroll
                for (int j = 0; j < 8; j++)
                    sH2[(to + i) * 64 + k0 + j] = fmaxf(acc[i][j] + bb, 0.f);
            }
        }
        __syncthreads();

        // ---- layer 3: 128 -> 256 (8 o x 8 k per thread) + atomicMax output --
        {
            int to = (tid >> 3) << 3, k0 = (tid & 7) << 3;
            float acc[8][8];
#pragma unroll
            for (int i = 0; i < 8; i++)
#pragma unroll
                for (int j = 0; j < 8; j++) acc[i][j] = 0.f;
#pragma unroll 4
            for (int c4 = 0; c4 < 32; c4++) {
                int c = c4 << 2;
                float4 a0 = *(const float4*)&sH2[(c + 0) * 64 + k0];
                float4 q0 = *(const float4*)&sH2[(c + 0) * 64 + k0 + 4];
                float4 a1 = *(const float4*)&sH2[(c + 1) * 64 + k0];
                float4 q1 = *(const float4*)&sH2[(c + 1) * 64 + k0 + 4];
                float4 a2 = *(const float4*)&sH2[(c + 2) * 64 + k0];
                float4 q2 = *(const float4*)&sH2[(c + 2) * 64 + k0 + 4];
                float4 a3 = *(const float4*)&sH2[(c + 3) * 64 + k0];
                float4 q3 = *(const float4*)&sH2[(c + 3) * 64 + k0 + 4];
#pragma unroll
                for (int i = 0; i < 8; i++) {
                    float4 w = *(const float4*)&sW3[(to + i) * 128 + c];
                    ACC8(acc[i], w.x, a0, q0)
                    ACC8(acc[i], w.y, a1, q1)
                    ACC8(acc[i], w.z, a2, q2)
                    ACC8(acc[i], w.w, a3, q3)
                }
            }
#pragma unroll
            for (int j = 0; j < 8; j++) {
                int ob = sOB[k0 + j];
                if (ob < 0) continue;
#pragma unroll
                for (int i = 0; i < 8; i++) {
                    float v = fmaxf(acc[i][j] + sB3[to + i], 0.f);
                    atomicMax((int*)out + ob + (to + i) * 4096, __float_as_int(v));
                }
            }
        }
    }
}

// ---------------- launch ----------------------------------------------------
extern "C" void kernel_launch(void* const* d_in, const int* in_sizes, int n_in,
                              void* d_out, int out_size)
{
    const float* seed = (const float*)d_in[0];
    const float* pc   = (const float*)d_in[1];
    const float* vp   = (const float*)d_in[2];
    float* out = (float*)d_out;

    // idempotent; first (non-captured) correctness call makes it stick
    cudaFuncSetAttribute(mlp_kernel, cudaFuncAttributeMaxDynamicSharedMemorySize, SMEM2_BYTES);

    prep_kernel<<<512, 256>>>(pc,
        (const float*)d_in[3],  (const float*)d_in[4],  (const float*)d_in[5],
        (const float*)d_in[6],  (const float*)d_in[7],  (const float*)d_in[8],
        (const float*)d_in[9],  (const float*)d_in[10], (const float*)d_in[11],
        (const float*)d_in[12], (const float*)d_in[13], (const float*)d_in[14],
        (const float*)d_in[15], (const float*)d_in[16], (const float*)d_in[17],
        (const float*)d_in[18], (const float*)d_in[19], (const float*)d_in[20],
        out);
    group_kernel<<<256, 256>>>(seed, vp);
    mlp_kernel<<<152, 256, SMEM2_BYTES>>>(out);
}

// round 11
// speedup vs baseline: 1.0041x; 1.0041x over previous
#include <cuda_runtime.h>

#define NPTS   16384
#define NBATCH 2
#define NSEED  1024
#define NDEPTH 4
#define NSAMP  64
#define NGRP   (NBATCH*NSEED*NDEPTH)   // 8192
#define OUTSZ  (NBATCH*256*NSEED*NDEPTH)

// ---------------- scratch (__device__ globals; no allocation allowed) -------
__device__ float    g_px[NBATCH][NPTS];
__device__ float    g_py[NBATCH][NPTS];
__device__ float    g_pz[NBATCH][NPTS];
__device__ float    g_groups[NGRP * 192];       // [g][c(3)][slot(64)]
__device__ unsigned g_wl[NGRP * NSAMP];         // worklist: g*64+slot
__device__ int      g_total;
__device__ float    g_w1f[192],   g_b1f[64];
__device__ float    g_w2f[8192],  g_b2f[128];
__device__ float    g_w3f[32768], g_b3f[256];

// ---------------- kernel 0: fold BN into weights, SoA transpose, zero out ---
__global__ void prep_kernel(
    const float* __restrict__ pc,
    const float* __restrict__ w1, const float* __restrict__ b1, const float* __restrict__ ga1,
    const float* __restrict__ be1, const float* __restrict__ m1, const float* __restrict__ v1,
    const float* __restrict__ w2, const float* __restrict__ b2, const float* __restrict__ ga2,
    const float* __restrict__ be2, const float* __restrict__ m2, const float* __restrict__ v2,
    const float* __restrict__ w3, const float* __restrict__ b3, const float* __restrict__ ga3,
    const float* __restrict__ be3, const float* __restrict__ m3, const float* __restrict__ v3,
    float* __restrict__ out)
{
    int tid = blockIdx.x * blockDim.x + threadIdx.x;
    int stride = gridDim.x * blockDim.x;
    for (int i = tid; i < 192; i += stride)   { int o = i / 3;  g_w1f[i] = w1[i] * (ga1[o] * rsqrtf(v1[o] + 1e-5f)); }
    for (int i = tid; i < 64; i += stride)    { float s = ga1[i] * rsqrtf(v1[i] + 1e-5f); g_b1f[i] = (b1[i] - m1[i]) * s + be1[i]; }
    for (int i = tid; i < 8192; i += stride)  { int o = i >> 6; g_w2f[i] = w2[i] * (ga2[o] * rsqrtf(v2[o] + 1e-5f)); }
    for (int i = tid; i < 128; i += stride)   { float s = ga2[i] * rsqrtf(v2[i] + 1e-5f); g_b2f[i] = (b2[i] - m2[i]) * s + be2[i]; }
    for (int i = tid; i < 32768; i += stride) { int o = i >> 7; g_w3f[i] = w3[i] * (ga3[o] * rsqrtf(v3[o] + 1e-5f)); }
    for (int i = tid; i < 256; i += stride)   { float s = ga3[i] * rsqrtf(v3[i] + 1e-5f); g_b3f[i] = (b3[i] - m3[i]) * s + be3[i]; }
    for (int i = tid; i < NBATCH * NPTS; i += stride) {
        int b = i >> 14, n = i & (NPTS - 1);
        const float* p = pc + (size_t)i * 3;
        g_px[b][n] = p[0]; g_py[b][n] = p[1]; g_pz[b][n] = p[2];
    }
    for (int i = tid; i < OUTSZ; i += stride) out[i] = 0.0f;
    if (tid == 0) g_total = 0;
}

// ---------------- kernel 1: warp-per-seed ordered cylinder selection --------
__global__ void __launch_bounds__(256) group_kernel(
    const float* __restrict__ seed_xyz, const float* __restrict__ vp_rot)
{
    int warp = blockIdx.x * 8 + (threadIdx.x >> 5);   // 0..2047 = b*1024+s
    int lane = threadIdx.x & 31;
    int b = warp >> 10;

    const float* sp = seed_xyz + (size_t)warp * 3;
    float sx = sp[0], sy = sp[1], sz = sp[2];
    const float* R = vp_rot + (size_t)warp * 9;        // R[c][d]
    float r00 = R[0], r01 = R[1], r02 = R[2];
    float r10 = R[3], r11 = R[4], r12 = R[5];
    float r20 = R[6], r21 = R[7], r22 = R[8];

    const float* __restrict__ px = g_px[b];
    const float* __restrict__ py = g_py[b];
    const float* __restrict__ pz = g_pz[b];

    int c0 = 0, c1 = 0, c2 = 0, c3 = 0;
    unsigned lm = (1u << lane) - 1u;
    float* gb = g_groups + (size_t)warp * (4 * 192);

    for (int n0 = 0; n0 < NPTS; n0 += 32) {
        int n = n0 + lane;
        float dx = px[n] - sx, dy = py[n] - sy, dz = pz[n] - sz;
        float h  = dx * r00 + dy * r10 + dz * r20;
        float yy = dx * r01 + dy * r11 + dz * r21;
        float zz = dx * r02 + dy * r12 + dz * r22;
        bool bs = (yy * yy + zz * zz < 0.0025f) && (h > -0.02f);
        unsigned bal; bool m;
        m = bs && (h < 0.01f); bal = __ballot_sync(0xffffffffu, m);
        if (bal) { int slot = c0 + __popc(bal & lm); if (m && slot < 64) { float* o = gb + slot;       o[0] = h; o[64] = yy; o[128] = zz; } c0 += __popc(bal); }
        m = bs && (h < 0.02f); bal = __ballot_sync(0xffffffffu, m);
        if (bal) { int slot = c1 + __popc(bal & lm); if (m && slot < 64) { float* o = gb + 192 + slot; o[0] = h; o[64] = yy; o[128] = zz; } c1 += __popc(bal); }
        m = bs && (h < 0.03f); bal = __ballot_sync(0xffffffffu, m);
        if (bal) { int slot = c2 + __popc(bal & lm); if (m && slot < 64) { float* o = gb + 384 + slot; o[0] = h; o[64] = yy; o[128] = zz; } c2 += __popc(bal); }
        m = bs && (h < 0.04f); bal = __ballot_sync(0xffffffffu, m);
        if (bal) { int slot = c3 + __popc(bal & lm); if (m && slot < 64) { float* o = gb + 576 + slot; o[0] = h; o[64] = yy; o[128] = zz; } c3 += __popc(bal); }
        if (c0 >= 64) break;   // masks nested: c0 <= c1 <= c2 <= c3
    }

    // fallback value = d_rot of point 0 (reference pads with index 0 if empty)
    float fdx = px[0] - sx, fdy = py[0] - sy, fdz = pz[0] - sz;
    float h0 = fdx * r00 + fdy * r10 + fdz * r20;
    float y0 = fdx * r01 + fdy * r11 + fdz * r21;
    float z0 = fdx * r02 + fdy * r12 + fdz * r22;

    int cnt[4] = {c0, c1, c2, c3};
    int eff[4], tot = 0;
#pragma unroll
    for (int d = 0; d < 4; d++) {
        int e = cnt[d] < 64 ? cnt[d] : 64;
        if (e == 0) {
            if (lane == 0) { float* o = gb + d * 192; o[0] = h0; o[64] = y0; o[128] = z0; }
            e = 1;   // padding duplicates first value; max over dupes == single sample
        }
        eff[d] = e; tot += e;
    }
    int base = 0;
    if (lane == 0) base = atomicAdd(&g_total, tot);
    base = __shfl_sync(0xffffffffu, base, 0);
#pragma unroll
    for (int d = 0; d < 4; d++) {
        unsigned gid = (unsigned)(warp * 4 + d) * 64u;
        for (int sl = lane; sl < eff[d]; sl += 32) g_wl[base + sl] = gid + (unsigned)sl;
        base += eff[d];
    }
}

// ---------------- kernel 2: persistent fused MLP over the sample worklist ---
#define SMEM2_FLOATS (8192 + 32768 + 192 + 64 + 128 + 256 + 192 + 4096 + 8192 + 64)
#define SMEM2_BYTES  (SMEM2_FLOATS * 4)

#define ACC8(A, wc, p, q)                                              \
    (A)[0] += (wc) * (p).x; (A)[1] += (wc) * (p).y;                    \
    (A)[2] += (wc) * (p).z; (A)[3] += (wc) * (p).w;                    \
    (A)[4] += (wc) * (q).x; (A)[5] += (wc) * (q).y;                    \
    (A)[6] += (wc) * (q).z; (A)[7] += (wc) * (q).w;

__global__ void __launch_bounds__(256, 1) mlp_kernel(float* __restrict__ out)
{
    extern __shared__ float sm[];
    float* sW2 = sm;                 // 8192
    float* sW3 = sW2 + 8192;         // 32768
    float* sW1 = sW3 + 32768;        // 192
    float* sB1 = sW1 + 192;          // 64
    float* sB2 = sB1 + 64;           // 128
    float* sB3 = sB2 + 128;          // 256
    float* sX  = sB3 + 256;          // 192  (3 x 64)
    float* sH1 = sX + 192;           // 4096 (64 x 64)
    float* sH2 = sH1 + 4096;         // 8192 (128 x 64)
    int*   sOB = (int*)(sH2 + 8192); // 64

    int tid = threadIdx.x;
    for (int i = tid; i < 8192; i += 256)  sW2[i] = g_w2f[i];
    for (int i = tid; i < 32768; i += 256) sW3[i] = g_w3f[i];
    if (tid < 192) sW1[tid] = g_w1f[tid];
    if (tid < 64)  sB1[tid] = g_b1f[tid];
    if (tid < 128) sB2[tid] = g_b2f[tid];
    sB3[tid] = g_b3f[tid];

    int total = g_total;
    int nb = (total + 63) >> 6;

    for (int bt = blockIdx.x; bt < nb; bt += gridDim.x) {
        __syncthreads();
        if (tid < 64) {
            int k = bt * 64 + tid;
            if (k < total) {
                unsigned e = g_wl[k];
                unsigned g4 = e >> 6, slot = e & 63u;
                const float* s = g_groups + (size_t)g4 * 192 + slot;
                sX[tid] = s[0]; sX[64 + tid] = s[64]; sX[128 + tid] = s[128];
                int bb = (int)(g4 >> 12), ss = (int)((g4 >> 2) & 1023), dd = (int)(g4 & 3);
                sOB[tid] = bb * 1048576 + ss * 4 + dd;   // + o*4096 later
            } else {
                sX[tid] = 0.f; sX[64 + tid] = 0.f; sX[128 + tid] = 0.f; sOB[tid] = -1;
            }
        }
        __syncthreads();

        // ---- layer 1: 3 -> 64 ----
        {
            int o = tid >> 2, k0 = (tid & 3) << 4;
            float w0 = sW1[o * 3], w1 = sW1[o * 3 + 1], w2 = sW1[o * 3 + 2], bb = sB1[o];
#pragma unroll
            for (int j = 0; j < 16; j++) {
                int k = k0 + j;
                float v = bb + w0 * sX[k] + w1 * sX[64 + k] + w2 * sX[128 + k];
                sH1[o * 64 + k] = fmaxf(v, 0.f);
            }
        }
        __syncthreads();

        // ---- layer 2: 64 -> 128 (4 o x 8 k per thread) ----
        {
            int to = (tid >> 3) << 2, k0 = (tid & 7) << 3;
            float acc[4][8];
#pragma unroll
            for (int i = 0; i < 4; i++)
#pragma unroll
                for (int j = 0; j < 8; j++) acc[i][j] = 0.f;
#pragma unroll 4
            for (int c4 = 0; c4 < 16; c4++) {
                int c = c4 << 2;
                float4 a0 = *(const float4*)&sH1[(c + 0) * 64 + k0];
                float4 q0 = *(const float4*)&sH1[(c + 0) * 64 + k0 + 4];
                float4 a1 = *(const float4*)&sH1[(c + 1) * 64 + k0];
                float4 q1 = *(const float4*)&sH1[(c + 1) * 64 + k0 + 4];
                float4 a2 = *(const float4*)&sH1[(c + 2) * 64 + k0];
                float4 q2 = *(const float4*)&sH1[(c + 2) * 64 + k0 + 4];
                float4 a3 = *(const float4*)&sH1[(c + 3) * 64 + k0];
                float4 q3 = *(const float4*)&sH1[(c + 3) * 64 + k0 + 4];
#pragma unroll
                for (int i = 0; i < 4; i++) {
                    float4 w = *(const float4*)&sW2[(to + i) * 64 + c];
                    ACC8(acc[i], w.x, a0, q0)
                    ACC8(acc[i], w.y, a1, q1)
                    ACC8(acc[i], w.z, a2, q2)
                    ACC8(acc[i], w.w, a3, q3)
                }
            }
#pragma unroll
            for (int i = 0; i < 4; i++) {
                float bb = sB2[to + i];
#pragma unroll
                for (int j = 0; j < 8; j++)
                    sH2[(to + i) * 64 + k0 + j] = fmaxf(acc[i][j] + bb, 0.f);
            }
        }
        __syncthreads();

        // ---- layer 3: 128 -> 256 (8 o x 8 k per thread) + atomicMax output --
        {
            int to = (tid >> 3) << 3, k0 = (tid & 7) << 3;
            float acc[8][8];
#pragma unroll
            for (int i = 0; i < 8; i++)
#pragma unroll
                for (int j = 0; j < 8; j++) acc[i][j] = 0.f;
#pragma unroll 4
            for (int c4 = 0; c4 < 32; c4++) {
                int c = c4 << 2;
                float4 a0 = *(const float4*)&sH2[(c + 0) * 64 + k0];
                float4 q0 = *(const float4*)&sH2[(c + 0) * 64 + k0 + 4];
                float4 a1 = *(const float4*)&sH2[(c + 1) * 64 + k0];
                float4 q1 = *(const float4*)&sH2[(c + 1) * 64 + k0 + 4];
                float4 a2 = *(const float4*)&sH2[(c + 2) * 64 + k0];
                float4 q2 = *(const float4*)&sH2[(c + 2) * 64 + k0 + 4];
                float4 a3 = *(const float4*)&sH2[(c + 3) * 64 + k0];
                float4 q3 = *(const float4*)&sH2[(c + 3) * 64 + k0 + 4];
#pragma unroll
                for (int i = 0; i < 8; i++) {
                    float4 w = *(const float4*)&sW3[(to + i) * 128 + c];
                    ACC8(acc[i], w.x, a0, q0)
                    ACC8(acc[i], w.y, a1, q1)
                    ACC8(acc[i], w.z, a2, q2)
                    ACC8(acc[i], w.w, a3, q3)
                }
            }
#pragma unroll
            for (int j = 0; j < 8; j++) {
                int ob = sOB[k0 + j];
                if (ob < 0) continue;
#pragma unroll
                for (int i = 0; i < 8; i++) {
                    float v = fmaxf(acc[i][j] + sB3[to + i], 0.f);
                    atomicMax((int*)out + ob + (to + i) * 4096, __float_as_int(v));
                }
            }
        }
    }
}

// ---------------- launch ----------------------------------------------------
extern "C" void kernel_launch(void* const* d_in, const int* in_sizes, int n_in,
                              void* d_out, int out_size)
{
    const float* seed = (const float*)d_in[0];
    const float* pc   = (const float*)d_in[1];
    const float* vp   = (const float*)d_in[2];
    float* out = (float*)d_out;

    // idempotent; first (non-captured) correctness call makes it stick
    cudaFuncSetAttribute(mlp_kernel, cudaFuncAttributeMaxDynamicSharedMemorySize, SMEM2_BYTES);

    prep_kernel<<<512, 256>>>(pc,
        (const float*)d_in[3],  (const float*)d_in[4],  (const float*)d_in[5],
        (const float*)d_in[6],  (const float*)d_in[7],  (const float*)d_in[8],
        (const float*)d_in[9],  (const float*)d_in[10], (const float*)d_in[11],
        (const float*)d_in[12], (const float*)d_in[13], (const float*)d_in[14],
        (const float*)d_in[15], (const float*)d_in[16], (const float*)d_in[17],
        (const float*)d_in[18], (const float*)d_in[19], (const float*)d_in[20],
        out);
    group_kernel<<<256, 256>>>(seed, vp);
    mlp_kernel<<<152, 256, SMEM2_BYTES>>>(out);
}

// round 12
// speedup vs baseline: 1.3617x; 1.3561x over previous
#include <cuda_runtime.h>

#define NPTS   16384
#define NBATCH 2
#define NSEED  1024
#define NSEEDT (NBATCH*NSEED)          // 2048
#define OUTSZ  (NBATCH*256*NSEED*4)
#define UCAP   256                     // max union samples per seed (4*64)

// ---------------- scratch (__device__ globals; no allocation allowed) -------
__device__ float    g_px[NBATCH][NPTS];
__device__ float    g_py[NBATCH][NPTS];
__device__ float    g_pz[NBATCH][NPTS];
__device__ float    g_uh[NSEEDT * UCAP];
__device__ float    g_uy[NSEEDT * UCAP];
__device__ float    g_uz[NSEEDT * UCAP];
__device__ unsigned char g_um[NSEEDT * UCAP];   // 4-bit depth membership mask
__device__ int      g_ucnt[NSEEDT];
__device__ unsigned g_wl[NSEEDT * UCAP + 64];   // worklist: seed<<8 | idx
__device__ int      g_total;
__device__ float    g_w1f[192],   g_b1f[64];
__device__ float    g_w2f[8192],  g_b2f[128];
__device__ float    g_w3f[32768], g_b3f[256];

// ---------------- f32x2 helpers (FFMA2 path: 2x fp32 FMA throughput) --------
__device__ __forceinline__ unsigned long long fma2(unsigned long long a,
                                                   unsigned long long b,
                                                   unsigned long long c) {
    unsigned long long d;
    asm("fma.rn.f32x2 %0, %1, %2, %3;" : "=l"(d) : "l"(a), "l"(b), "l"(c));
    return d;
}
__device__ __forceinline__ unsigned long long pack2(float x) {
    unsigned long long r;
    asm("mov.b64 %0, {%1, %1};" : "=l"(r) : "f"(x));
    return r;
}
__device__ __forceinline__ float2 u2f(unsigned long long v) {
    float2 f;
    asm("mov.b64 {%0, %1}, %2;" : "=f"(f.x), "=f"(f.y) : "l"(v));
    return f;
}

// ---------------- kernel 0: fold BN into weights, SoA transpose, zero out ---
__global__ void prep_kernel(
    const float* __restrict__ pc,
    const float* __restrict__ w1, const float* __restrict__ b1, const float* __restrict__ ga1,
    const float* __restrict__ be1, const float* __restrict__ m1, const float* __restrict__ v1,
    const float* __restrict__ w2, const float* __restrict__ b2, const float* __restrict__ ga2,
    const float* __restrict__ be2, const float* __restrict__ m2, const float* __restrict__ v2,
    const float* __restrict__ w3, const float* __restrict__ b3, const float* __restrict__ ga3,
    const float* __restrict__ be3, const float* __restrict__ m3, const float* __restrict__ v3,
    float* __restrict__ out)
{
    int tid = blockIdx.x * blockDim.x + threadIdx.x;
    int stride = gridDim.x * blockDim.x;
    for (int i = tid; i < 192; i += stride)   { int o = i / 3;  g_w1f[i] = w1[i] * (ga1[o] * rsqrtf(v1[o] + 1e-5f)); }
    for (int i = tid; i < 64; i += stride)    { float s = ga1[i] * rsqrtf(v1[i] + 1e-5f); g_b1f[i] = (b1[i] - m1[i]) * s + be1[i]; }
    for (int i = tid; i < 8192; i += stride)  { int o = i >> 6; g_w2f[i] = w2[i] * (ga2[o] * rsqrtf(v2[o] + 1e-5f)); }
    for (int i = tid; i < 128; i += stride)   { float s = ga2[i] * rsqrtf(v2[i] + 1e-5f); g_b2f[i] = (b2[i] - m2[i]) * s + be2[i]; }
    for (int i = tid; i < 32768; i += stride) { int o = i >> 7; g_w3f[i] = w3[i] * (ga3[o] * rsqrtf(v3[o] + 1e-5f)); }
    for (int i = tid; i < 256; i += stride)   { float s = ga3[i] * rsqrtf(v3[i] + 1e-5f); g_b3f[i] = (b3[i] - m3[i]) * s + be3[i]; }
    for (int i = tid; i < NBATCH * NPTS; i += stride) {
        int b = i >> 14, n = i & (NPTS - 1);
        const float* p = pc + (size_t)i * 3;
        g_px[b][n] = p[0]; g_py[b][n] = p[1]; g_pz[b][n] = p[2];
    }
    for (int i = tid; i < OUTSZ; i += stride) out[i] = 0.0f;
}

// ---------------- kernel 1: warp-per-seed dedup'd cylinder selection --------
// Emits the UNION of samples across the 4 depths, each with a 4-bit mask of
// which depths select it. Masks are nested (hmax ascending) so c0<=c1<=c2<=c3;
// once c0>=64 all depths are capped and nothing more can be selected.
__global__ void __launch_bounds__(256) group_kernel(
    const float* __restrict__ seed_xyz, const float* __restrict__ vp_rot)
{
    int warp = blockIdx.x * 8 + (threadIdx.x >> 5);   // 0..2047 = b*1024+s
    int lane = threadIdx.x & 31;
    int b = warp >> 10;

    const float* sp = seed_xyz + (size_t)warp * 3;
    float sx = sp[0], sy = sp[1], sz = sp[2];
    const float* R = vp_rot + (size_t)warp * 9;
    float r00 = R[0], r01 = R[1], r02 = R[2];
    float r10 = R[3], r11 = R[4], r12 = R[5];
    float r20 = R[6], r21 = R[7], r22 = R[8];

    const float* __restrict__ px = g_px[b];
    const float* __restrict__ py = g_py[b];
    const float* __restrict__ pz = g_pz[b];

    int c0 = 0, c1 = 0, c2 = 0, c3 = 0, u = 0;
    unsigned lm = (1u << lane) - 1u;
    int gbase = warp * UCAP;

    for (int n0 = 0; n0 < NPTS; n0 += 32) {
        int n = n0 + lane;
        float dx = px[n] - sx, dy = py[n] - sy, dz = pz[n] - sz;
        float h  = dx * r00 + dy * r10 + dz * r20;
        float yy = dx * r01 + dy * r11 + dz * r21;
        float zz = dx * r02 + dy * r12 + dz * r22;
        bool base = (yy * yy + zz * zz < 0.0025f) && (h > -0.02f) && (h < 0.04f);
        unsigned balb = __ballot_sync(0xffffffffu, base);
        if (balb == 0u) continue;                  // fast path (~92% of iters)

        unsigned b0 = __ballot_sync(0xffffffffu, base && h < 0.01f);
        unsigned b1 = __ballot_sync(0xffffffffu, base && h < 0.02f);
        unsigned b2 = __ballot_sync(0xffffffffu, base && h < 0.03f);
        unsigned b3 = balb;                        // base already implies h<0.04
        int bits = 0;
        if (base) {
            if (h < 0.01f && c0 + __popc(b0 & lm) < 64) bits |= 1;
            if (h < 0.02f && c1 + __popc(b1 & lm) < 64) bits |= 2;
            if (h < 0.03f && c2 + __popc(b2 & lm) < 64) bits |= 4;
            if (            c3 + __popc(b3 & lm) < 64) bits |= 8;
        }
        unsigned be = __ballot_sync(0xffffffffu, bits != 0);
        if (bits) {
            int slot = gbase + u + __popc(be & lm);
            g_uh[slot] = h; g_uy[slot] = yy; g_uz[slot] = zz;
            g_um[slot] = (unsigned char)bits;
        }
        u  += __popc(be);
        c0 += __popc(b0); c1 += __popc(b1); c2 += __popc(b2); c3 += __popc(b3);
        if (c0 >= 64) break;
    }

    // fallback: empty depths use d_rot of point 0 (reference pads with idx 0)
    int ebits = (c0 == 0 ? 1 : 0) | (c1 == 0 ? 2 : 0) | (c2 == 0 ? 4 : 0) | (c3 == 0 ? 8 : 0);
    if (ebits) {
        if (lane == 0) {
            float fdx = px[0] - sx, fdy = py[0] - sy, fdz = pz[0] - sz;
            int slot = gbase + u;
            g_uh[slot] = fdx * r00 + fdy * r10 + fdz * r20;
            g_uy[slot] = fdx * r01 + fdy * r11 + fdz * r21;
            g_uz[slot] = fdx * r02 + fdy * r12 + fdz * r22;
            g_um[slot] = (unsigned char)ebits;
        }
        u++;
    }
    if (lane == 0) g_ucnt[warp] = u;
}

// ---------------- kernel 1.5: pack worklist, seeds padded to 8-col units ----
__global__ void __launch_bounds__(1024) pack_kernel()
{
    __shared__ int soff[NSEEDT];
    __shared__ int wsum[32];
    int tid = threadIdx.x, lane = tid & 31, w = tid >> 5;

    int cA = (g_ucnt[2 * tid]     + 7) & ~7;   // pad each seed to multiple of 8
    int cB = (g_ucnt[2 * tid + 1] + 7) & ~7;
    int s = cA + cB;
    int v = s;
#pragma unroll
    for (int o = 1; o < 32; o <<= 1) { int t = __shfl_up_sync(0xffffffffu, v, o); if (lane >= o) v += t; }
    if (lane == 31) wsum[w] = v;
    __syncthreads();
    if (tid < 32) {
        int t = wsum[tid];
#pragma unroll
        for (int o = 1; o < 32; o <<= 1) { int x = __shfl_up_sync(0xffffffffu, t, o); if (tid >= o) t += x; }
        wsum[tid] = t;
    }
    __syncthreads();
    int excl = v - s + (w ? wsum[w - 1] : 0);
    soff[2 * tid] = excl; soff[2 * tid + 1] = excl + cA;
    __syncthreads();

    int total = wsum[31];
    for (int seed = tid; seed < NSEEDT; seed += 1024) {
        int basep = soff[seed], cnt = g_ucnt[seed], pc = (cnt + 7) & ~7;
        for (int p = 0; p < pc; p++) {
            int idx = p < cnt ? p : cnt - 1;   // pads replicate sample 0..: dup == identity for max
            g_wl[basep + p] = (unsigned)((seed << 8) | idx);
        }
    }
    int tot64 = (total + 63) & ~63;
    for (int i = total + tid; i < tot64; i += 1024) g_wl[i] = 0xffffffffu;
    if (tid == 0) g_total = tot64;
}

// ---------------- kernel 2: persistent fused MLP (f32x2) --------------------
#define SMEM2_FLOATS (8192 + 32768 + 192 + 64 + 128 + 256 + 192 + 4096 + 8192 + 64 + 8)
#define SMEM2_BYTES  (SMEM2_FLOATS * 4)

__global__ void __launch_bounds__(256, 1) mlp_kernel(float* __restrict__ out)
{
    extern __shared__ float sm[];
    float* sW2 = sm;                  // 8192
    float* sW3 = sW2 + 8192;          // 32768
    float* sW1 = sW3 + 32768;         // 192
    float* sB1 = sW1 + 192;           // 64
    float* sB2 = sB1 + 64;            // 128
    float* sB3 = sB2 + 128;           // 256
    float* sX  = sB3 + 256;           // 192  (3 x 64)
    float* sH1 = sX + 192;            // 4096 (64 x 64)
    float* sH2 = sH1 + 4096;          // 8192 (128 x 64)
    int*  sMask = (int*)(sH2 + 8192); // 64
    int*  sOB   = sMask + 64;         // 8 (per 8-col unit: output base or -1)

    int tid = threadIdx.x;
    for (int i = tid; i < 8192; i += 256)  sW2[i] = g_w2f[i];
    for (int i = tid; i < 32768; i += 256) sW3[i] = g_w3f[i];
    if (tid < 192) sW1[tid] = g_w1f[tid];
    if (tid < 64)  sB1[tid] = g_b1f[tid];
    if (tid < 128) sB2[tid] = g_b2f[tid];
    sB3[tid] = g_b3f[tid];

    int nb = g_total >> 6;

    for (int bt = blockIdx.x; bt < nb; bt += gridDim.x) {
        __syncthreads();
        if (tid < 64) {
            unsigned e = g_wl[bt * 64 + tid];
            int seed = -1;
            if (e != 0xffffffffu) {
                seed = (int)(e >> 8);
                int gi = seed * UCAP + (int)(e & 255u);
                sX[tid] = g_uh[gi]; sX[64 + tid] = g_uy[gi]; sX[128 + tid] = g_uz[gi];
                sMask[tid] = (int)g_um[gi];
            } else {
                sX[tid] = 0.f; sX[64 + tid] = 0.f; sX[128 + tid] = 0.f; sMask[tid] = 0;
            }
            if ((tid & 7) == 0)
                sOB[tid >> 3] = (seed < 0) ? -1 : ((seed >> 10) * 1048576 + (seed & 1023) * 4);
        }
        __syncthreads();

        // ---- layer 1: 3 -> 64 ----
        {
            int o = tid >> 2, k0 = (tid & 3) << 4;
            float w0 = sW1[o * 3], w1 = sW1[o * 3 + 1], w2 = sW1[o * 3 + 2], bb = sB1[o];
#pragma unroll
            for (int j = 0; j < 16; j++) {
                int k = k0 + j;
                float v = bb + w0 * sX[k] + w1 * sX[64 + k] + w2 * sX[128 + k];
                sH1[o * 64 + k] = fmaxf(v, 0.f);
            }
        }
        __syncthreads();

        // ---- layer 2: 64 -> 128, f32x2, 4o x 8k per thread ----
        {
            int to = (tid >> 3) << 2, k0 = (tid & 7) << 3;
            unsigned long long acc[4][4];
#pragma unroll
            for (int i = 0; i < 4; i++)
#pragma unroll
                for (int q = 0; q < 4; q++) acc[i][q] = 0ull;
#pragma unroll 4
            for (int c4 = 0; c4 < 16; c4++) {
                int c = c4 << 2;
                ulonglong2 A[4][2];
#pragma unroll
                for (int cc = 0; cc < 4; cc++) {
                    A[cc][0] = *(const ulonglong2*)&sH1[(c + cc) * 64 + k0];
                    A[cc][1] = *(const ulonglong2*)&sH1[(c + cc) * 64 + k0 + 4];
                }
#pragma unroll
                for (int i = 0; i < 4; i++) {
                    float4 wv = *(const float4*)&sW2[(to + i) * 64 + c];
                    unsigned long long w0 = pack2(wv.x), w1 = pack2(wv.y),
                                       w2 = pack2(wv.z), w3 = pack2(wv.w);
                    acc[i][0] = fma2(w0, A[0][0].x, acc[i][0]);
                    acc[i][1] = fma2(w0, A[0][0].y, acc[i][1]);
                    acc[i][2] = fma2(w0, A[0][1].x, acc[i][2]);
                    acc[i][3] = fma2(w0, A[0][1].y, acc[i][3]);
                    acc[i][0] = fma2(w1, A[1][0].x, acc[i][0]);
                    acc[i][1] = fma2(w1, A[1][0].y, acc[i][1]);
                    acc[i][2] = fma2(w1, A[1][1].x, acc[i][2]);
                    acc[i][3] = fma2(w1, A[1][1].y, acc[i][3]);
                    acc[i][0] = fma2(w2, A[2][0].x, acc[i][0]);
                    acc[i][1] = fma2(w2, A[2][0].y, acc[i][1]);
                    acc[i][2] = fma2(w2, A[2][1].x, acc[i][2]);
                    acc[i][3] = fma2(w2, A[2][1].y, acc[i][3]);
                    acc[i][0] = fma2(w3, A[3][0].x, acc[i][0]);
                    acc[i][1] = fma2(w3, A[3][0].y, acc[i][1]);
                    acc[i][2] = fma2(w3, A[3][1].x, acc[i][2]);
                    acc[i][3] = fma2(w3, A[3][1].y, acc[i][3]);
                }
            }
#pragma unroll
            for (int i = 0; i < 4; i++) {
                float bb = sB2[to + i];
#pragma unroll
                for (int q = 0; q < 4; q++) {
                    float2 f = u2f(acc[i][q]);
                    float2 o2; o2.x = fmaxf(f.x + bb, 0.f); o2.y = fmaxf(f.y + bb, 0.f);
                    *(float2*)&sH2[(to + i) * 64 + k0 + 2 * q] = o2;
                }
            }
        }
        __syncthreads();

        // ---- layer 3: 128 -> 256, f32x2, 8o x 8k + depth-masked max + RED ---
        {
            int to = (tid >> 3) << 3, k0 = (tid & 7) << 3;
            unsigned long long acc[8][4];
#pragma unroll
            for (int i = 0; i < 8; i++)
#pragma unroll
                for (int q = 0; q < 4; q++) acc[i][q] = 0ull;
#pragma unroll 2
            for (int c4 = 0; c4 < 32; c4++) {
                int c = c4 << 2;
                ulonglong2 A[4][2];
#pragma unroll
                for (int cc = 0; cc < 4; cc++) {
                    A[cc][0] = *(const ulonglong2*)&sH2[(c + cc) * 64 + k0];
                    A[cc][1] = *(const ulonglong2*)&sH2[(c + cc) * 64 + k0 + 4];
                }
#pragma unroll
                for (int i = 0; i < 8; i++) {
                    float4 wv = *(const float4*)&sW3[(to + i) * 128 + c];
                    unsigned long long w0 = pack2(wv.x), w1 = pack2(wv.y),
                                       w2 = pack2(wv.z), w3 = pack2(wv.w);
                    acc[i][0] = fma2(w0, A[0][0].x, acc[i][0]);
                    acc[i][1] = fma2(w0, A[0][0].y, acc[i][1]);
                    acc[i][2] = fma2(w0, A[0][1].x, acc[i][2]);
                    acc[i][3] = fma2(w0, A[0][1].y, acc[i][3]);
                    acc[i][0] = fma2(w1, A[1][0].x, acc[i][0]);
                    acc[i][1] = fma2(w1, A[1][0].y, acc[i][1]);
                    acc[i][2] = fma2(w1, A[1][1].x, acc[i][2]);
                    acc[i][3] = fma2(w1, A[1][1].y, acc[i][3]);
                    acc[i][0] = fma2(w2, A[2][0].x, acc[i][0]);
                    acc[i][1] = fma2(w2, A[2][0].y, acc[i][1]);
                    acc[i][2] = fma2(w2, A[2][1].x, acc[i][2]);
                    acc[i][3] = fma2(w2, A[2][1].y, acc[i][3]);
                    acc[i][0] = fma2(w3, A[3][0].x, acc[i][0]);
                    acc[i][1] = fma2(w3, A[3][0].y, acc[i][1]);
                    acc[i][2] = fma2(w3, A[3][1].x, acc[i][2]);
                    acc[i][3] = fma2(w3, A[3][1].y, acc[i][3]);
                }
            }
            // epilogue: bias+relu, reduce max per depth over this thread's 8 cols
            float b3r[8];
#pragma unroll
            for (int i = 0; i < 8; i++) b3r[i] = sB3[to + i];
            int mk[8];
#pragma unroll
            for (int j = 0; j < 8; j++) mk[j] = sMask[k0 + j];
            int ub = mk[0] | mk[1] | mk[2] | mk[3] | mk[4] | mk[5] | mk[6] | mk[7];
            float vm[4][8];
#pragma unroll
            for (int d = 0; d < 4; d++)
#pragma unroll
                for (int i = 0; i < 8; i++) vm[d][i] = 0.f;
#pragma unroll
            for (int q = 0; q < 4; q++) {
                int m0 = mk[2 * q], m1 = mk[2 * q + 1];
#pragma unroll
                for (int i = 0; i < 8; i++) {
                    float2 f = u2f(acc[i][q]);
                    float va = fmaxf(f.x + b3r[i], 0.f);
                    float vb = fmaxf(f.y + b3r[i], 0.f);
                    if (m0 & 1) vm[0][i] = fmaxf(vm[0][i], va);
                    if (m0 & 2) vm[1][i] = fmaxf(vm[1][i], va);
                    if (m0 & 4) vm[2][i] = fmaxf(vm[2][i], va);
                    if (m0 & 8) vm[3][i] = fmaxf(vm[3][i], va);
                    if (m1 & 1) vm[0][i] = fmaxf(vm[0][i], vb);
                    if (m1 & 2) vm[1][i] = fmaxf(vm[1][i], vb);
                    if (m1 & 4) vm[2][i] = fmaxf(vm[2][i], vb);
                    if (m1 & 8) vm[3][i] = fmaxf(vm[3][i], vb);
                }
            }
            int ob = sOB[tid & 7];
            if (ob >= 0) {
#pragma unroll
                for (int d = 0; d < 4; d++) {
                    if ((ub >> d) & 1) {
                        int* op = (int*)out + ob + d;
#pragma unroll
                        for (int i = 0; i < 8; i++)
                            atomicMax(op + (to + i) * 4096, __float_as_int(vm[d][i]));
                    }
                }
            }
        }
    }
}

// ---------------- launch ----------------------------------------------------
extern "C" void kernel_launch(void* const* d_in, const int* in_sizes, int n_in,
                              void* d_out, int out_size)
{
    const float* seed = (const float*)d_in[0];
    const float* pc   = (const float*)d_in[1];
    const float* vp   = (const float*)d_in[2];
    float* out = (float*)d_out;

    cudaFuncSetAttribute(mlp_kernel, cudaFuncAttributeMaxDynamicSharedMemorySize, SMEM2_BYTES);

    prep_kernel<<<512, 256>>>(pc,
        (const float*)d_in[3],  (const float*)d_in[4],  (const float*)d_in[5],
        (const float*)d_in[6],  (const float*)d_in[7],  (const float*)d_in[8],
        (const float*)d_in[9],  (const float*)d_in[10], (const float*)d_in[11],
        (const float*)d_in[12], (const float*)d_in[13], (const float*)d_in[14],
        (const float*)d_in[15], (const float*)d_in[16], (const float*)d_in[17],
        (const float*)d_in[18], (const float*)d_in[19], (const float*)d_in[20],
        out);
    group_kernel<<<256, 256>>>(seed, vp);
    pack_kernel<<<1, 1024>>>();
    mlp_kernel<<<152, 256, SMEM2_BYTES>>>(out);
}

// round 13
// speedup vs baseline: 2.3840x; 1.7507x over previous
#include <cuda_runtime.h>

#define NPTS   16384
#define NBATCH 2
#define NSEED  1024
#define NSEEDT (NBATCH*NSEED)          // 2048
#define OUTSZ  (NBATCH*256*NSEED*4)
#define UCAP   256                     // max union samples per seed (4*64)

// ---------------- scratch (__device__ globals; no allocation allowed) -------
__device__ float    g_px[NBATCH][NPTS];
__device__ float    g_py[NBATCH][NPTS];
__device__ float    g_pz[NBATCH][NPTS];
__device__ float    g_uh[NSEEDT * UCAP];
__device__ float    g_uy[NSEEDT * UCAP];
__device__ float    g_uz[NSEEDT * UCAP];
__device__ unsigned char g_um[NSEEDT * UCAP];   // 4-bit depth membership mask
__device__ int      g_ucnt[NSEEDT];
__device__ unsigned g_wl[NSEEDT * UCAP + 64];   // worklist: seed<<8 | idx
__device__ int      g_total;
__device__ float    g_w1f[192],   g_b1f[64];
__device__ float    g_w2f[8192],  g_b2f[128];
__device__ float    g_w3f[32768], g_b3f[256];

// ---------------- f32x2 helpers (FFMA2 path: 2x fp32 FMA throughput) --------
__device__ __forceinline__ unsigned long long fma2(unsigned long long a,
                                                   unsigned long long b,
                                                   unsigned long long c) {
    unsigned long long d;
    asm("fma.rn.f32x2 %0, %1, %2, %3;" : "=l"(d) : "l"(a), "l"(b), "l"(c));
    return d;
}
__device__ __forceinline__ unsigned long long pack2(float x) {
    unsigned long long r;
    asm("mov.b64 %0, {%1, %1};" : "=l"(r) : "f"(x));
    return r;
}
__device__ __forceinline__ float2 u2f(unsigned long long v) {
    float2 f;
    asm("mov.b64 {%0, %1}, %2;" : "=f"(f.x), "=f"(f.y) : "l"(v));
    return f;
}

// ---------------- kernel 0: fold BN into weights, SoA transpose, zero out ---
__global__ void prep_kernel(
    const float* __restrict__ pc,
    const float* __restrict__ w1, const float* __restrict__ b1, const float* __restrict__ ga1,
    const float* __restrict__ be1, const float* __restrict__ m1, const float* __restrict__ v1,
    const float* __restrict__ w2, const float* __restrict__ b2, const float* __restrict__ ga2,
    const float* __restrict__ be2, const float* __restrict__ m2, const float* __restrict__ v2,
    const float* __restrict__ w3, const float* __restrict__ b3, const float* __restrict__ ga3,
    const float* __restrict__ be3, const float* __restrict__ m3, const float* __restrict__ v3,
    float* __restrict__ out)
{
    int tid = blockIdx.x * blockDim.x + threadIdx.x;
    int stride = gridDim.x * blockDim.x;
    for (int i = tid; i < 192; i += stride)   { int o = i / 3;  g_w1f[i] = w1[i] * (ga1[o] * rsqrtf(v1[o] + 1e-5f)); }
    for (int i = tid; i < 64; i += stride)    { float s = ga1[i] * rsqrtf(v1[i] + 1e-5f); g_b1f[i] = (b1[i] - m1[i]) * s + be1[i]; }
    for (int i = tid; i < 8192; i += stride)  { int o = i >> 6; g_w2f[i] = w2[i] * (ga2[o] * rsqrtf(v2[o] + 1e-5f)); }
    for (int i = tid; i < 128; i += stride)   { float s = ga2[i] * rsqrtf(v2[i] + 1e-5f); g_b2f[i] = (b2[i] - m2[i]) * s + be2[i]; }
    for (int i = tid; i < 32768; i += stride) { int o = i >> 7; g_w3f[i] = w3[i] * (ga3[o] * rsqrtf(v3[o] + 1e-5f)); }
    for (int i = tid; i < 256; i += stride)   { float s = ga3[i] * rsqrtf(v3[i] + 1e-5f); g_b3f[i] = (b3[i] - m3[i]) * s + be3[i]; }
    for (int i = tid; i < NBATCH * NPTS; i += stride) {
        int b = i >> 14, n = i & (NPTS - 1);
        const float* p = pc + (size_t)i * 3;
        g_px[b][n] = p[0]; g_py[b][n] = p[1]; g_pz[b][n] = p[2];
    }
    for (int i = tid; i < OUTSZ; i += stride) out[i] = 0.0f;
}

// ---------------- kernel 1: 4-warps-per-seed dedup'd cylinder selection -----
// Phase 1: each warp scans a contiguous quarter (4096 pts) with prefetch,
// keeping candidates whose per-quarter per-depth rank < 64 (superset of the
// globally-selected set). Phase 2: warp 0 replays the ordered candidate list
// with global counters — identical selection semantics to the reference.
__global__ void __launch_bounds__(128) group_kernel(
    const float* __restrict__ seed_xyz, const float* __restrict__ vp_rot)
{
    __shared__ float sCh[4][256], sCy[4][256], sCz[4][256];
    __shared__ int   sCnt[4];

    int seed = blockIdx.x;                 // 0..2047 = b*1024+s
    int lane = threadIdx.x & 31, w = threadIdx.x >> 5;
    int b = seed >> 10;

    const float* sp = seed_xyz + (size_t)seed * 3;
    float sx = sp[0], sy = sp[1], sz = sp[2];
    const float* R = vp_rot + (size_t)seed * 9;
    float r00 = R[0], r01 = R[1], r02 = R[2];
    float r10 = R[3], r11 = R[4], r12 = R[5];
    float r20 = R[6], r21 = R[7], r22 = R[8];

    const float* __restrict__ px = g_px[b];
    const float* __restrict__ py = g_py[b];
    const float* __restrict__ pz = g_pz[b];

    unsigned lm = (1u << lane) - 1u;

    // ---------- phase 1 ----------
    {
        int start = w * 4096, end = start + 4096;
        int c0 = 0, c1 = 0, c2 = 0, c3 = 0, cnt = 0;
        float nx = px[start + lane], ny = py[start + lane], nz = pz[start + lane];
        for (int n0 = start; n0 < end; n0 += 32) {
            float X = nx, Y = ny, Z = nz;
            int np = (n0 + 32 < end) ? (n0 + 32 + lane) : (start + lane);
            nx = px[np]; ny = py[np]; nz = pz[np];     // prefetch: breaks load-use chain

            float dx = X - sx, dy = Y - sy, dz = Z - sz;
            float h  = dx * r00 + dy * r10 + dz * r20;
            float yy = dx * r01 + dy * r11 + dz * r21;
            float zz = dx * r02 + dy * r12 + dz * r22;
            bool base = (yy * yy + zz * zz < 0.0025f) && (h > -0.02f) && (h < 0.04f);
            unsigned bb = __ballot_sync(0xffffffffu, base);
            if (bb) {
                unsigned m0 = __ballot_sync(0xffffffffu, base && h < 0.01f);
                unsigned m1 = __ballot_sync(0xffffffffu, base && h < 0.02f);
                unsigned m2 = __ballot_sync(0xffffffffu, base && h < 0.03f);
                bool keep = false;
                if (base) {
                    keep = (h < 0.01f && c0 + __popc(m0 & lm) < 64)
                        || (h < 0.02f && c1 + __popc(m1 & lm) < 64)
                        || (h < 0.03f && c2 + __popc(m2 & lm) < 64)
                        || (c3 + __popc(bb & lm) < 64);
                }
                unsigned bk = __ballot_sync(0xffffffffu, keep);
                if (keep) {
                    int s = cnt + __popc(bk & lm);
                    sCh[w][s] = h; sCy[w][s] = yy; sCz[w][s] = zz;
                }
                cnt += __popc(bk);
                c0 += __popc(m0); c1 += __popc(m1); c2 += __popc(m2); c3 += __popc(bb);
                if (c0 >= 64) break;       // all local depth caps reached
            }
        }
        if (lane == 0) sCnt[w] = cnt;
    }
    __syncthreads();

    // ---------- phase 2 (warp 0 only) ----------
    if (w == 0) {
        int c0 = 0, c1 = 0, c2 = 0, c3 = 0, u = 0;
        int gbase = seed * UCAP;
#pragma unroll 1
        for (int q = 0; q < 4; q++) {
            int n = sCnt[q];
            for (int i0 = 0; i0 < n; i0 += 32) {
                int i = i0 + lane;
                bool v = i < n;
                float h  = v ? sCh[q][i] : 1e9f;
                float yy = v ? sCy[q][i] : 0.f;
                float zz = v ? sCz[q][i] : 0.f;
                unsigned m3 = __ballot_sync(0xffffffffu, v);
                unsigned m0 = __ballot_sync(0xffffffffu, v && h < 0.01f);
                unsigned m1 = __ballot_sync(0xffffffffu, v && h < 0.02f);
                unsigned m2 = __ballot_sync(0xffffffffu, v && h < 0.03f);
                int bits = 0;
                if (v) {
                    if (h < 0.01f && c0 + __popc(m0 & lm) < 64) bits |= 1;
                    if (h < 0.02f && c1 + __popc(m1 & lm) < 64) bits |= 2;
                    if (h < 0.03f && c2 + __popc(m2 & lm) < 64) bits |= 4;
                    if (            c3 + __popc(m3 & lm) < 64) bits |= 8;
                }
                unsigned be = __ballot_sync(0xffffffffu, bits != 0);
                if (bits) {
                    int s = gbase + u + __popc(be & lm);
                    g_uh[s] = h; g_uy[s] = yy; g_uz[s] = zz;
                    g_um[s] = (unsigned char)bits;
                }
                u  += __popc(be);
                c0 += __popc(m0); c1 += __popc(m1); c2 += __popc(m2); c3 += __popc(m3);
            }
        }
        // fallback: empty depths use d_rot of point 0 (reference pads with idx 0)
        int ebits = (c0 == 0 ? 1 : 0) | (c1 == 0 ? 2 : 0) | (c2 == 0 ? 4 : 0) | (c3 == 0 ? 8 : 0);
        if (ebits) {
            if (lane == 0) {
                float fdx = px[0] - sx, fdy = py[0] - sy, fdz = pz[0] - sz;
                int s = gbase + u;
                g_uh[s] = fdx * r00 + fdy * r10 + fdz * r20;
                g_uy[s] = fdx * r01 + fdy * r11 + fdz * r21;
                g_uz[s] = fdx * r02 + fdy * r12 + fdz * r22;
                g_um[s] = (unsigned char)ebits;
            }
            u++;
        }
        if (lane == 0) g_ucnt[seed] = u;
    }
}

// ---------------- kernel 1.5: pack worklist, seeds padded to 4-col units ----
__global__ void __launch_bounds__(1024) pack_kernel()
{
    __shared__ int soff[NSEEDT];
    __shared__ int wsum[32];
    int tid = threadIdx.x, lane = tid & 31, w = tid >> 5;

    int cA = (g_ucnt[2 * tid]     + 3) & ~3;   // pad each seed to multiple of 4
    int cB = (g_ucnt[2 * tid + 1] + 3) & ~3;
    int s = cA + cB;
    int v = s;
#pragma unroll
    for (int o = 1; o < 32; o <<= 1) { int t = __shfl_up_sync(0xffffffffu, v, o); if (lane >= o) v += t; }
    if (lane == 31) wsum[w] = v;
    __syncthreads();
    if (tid < 32) {
        int t = wsum[tid];
#pragma unroll
        for (int o = 1; o < 32; o <<= 1) { int x = __shfl_up_sync(0xffffffffu, t, o); if (tid >= o) t += x; }
        wsum[tid] = t;
    }
    __syncthreads();
    int excl = v - s + (w ? wsum[w - 1] : 0);
    soff[2 * tid] = excl; soff[2 * tid + 1] = excl + cA;
    __syncthreads();

    int total = wsum[31];
    for (int seed = tid; seed < NSEEDT; seed += 1024) {
        int basep = soff[seed], cnt = g_ucnt[seed], pc = (cnt + 3) & ~3;
        for (int p = 0; p < pc; p++) {
            int idx = p < cnt ? p : cnt - 1;   // pads replicate a sample: dup == identity for max
            g_wl[basep + p] = (unsigned)((seed << 8) | idx);
        }
    }
    int tot64 = (total + 63) & ~63;
    for (int i = total + tid; i < tot64; i += 1024) g_wl[i] = 0xffffffffu;
    if (tid == 0) g_total = tot64;
}

// ---------------- kernel 2: persistent fused MLP (f32x2) --------------------
#define SMEM2_FLOATS (8192 + 32768 + 192 + 64 + 128 + 256 + 192 + 4096 + 8192 + 64 + 16)
#define SMEM2_BYTES  (SMEM2_FLOATS * 4)

__global__ void __launch_bounds__(256, 1) mlp_kernel(float* __restrict__ out)
{
    extern __shared__ float sm[];
    float* sW2 = sm;                  // 8192
    float* sW3 = sW2 + 8192;          // 32768
    float* sW1 = sW3 + 32768;         // 192
    float* sB1 = sW1 + 192;           // 64
    float* sB2 = sB1 + 64;            // 128
    float* sB3 = sB2 + 128;           // 256
    float* sX  = sB3 + 256;           // 192  (3 x 64)
    float* sH1 = sX + 192;            // 4096 (64 x 64)
    float* sH2 = sH1 + 4096;          // 8192 (128 x 64)
    int*  sMask = (int*)(sH2 + 8192); // 64
    int*  sOB   = sMask + 64;         // 16 (per 4-col unit: output base or -1)

    int tid = threadIdx.x;
    for (int i = tid; i < 8192; i += 256)  sW2[i] = g_w2f[i];
    for (int i = tid; i < 32768; i += 256) sW3[i] = g_w3f[i];
    if (tid < 192) sW1[tid] = g_w1f[tid];
    if (tid < 64)  sB1[tid] = g_b1f[tid];
    if (tid < 128) sB2[tid] = g_b2f[tid];
    sB3[tid] = g_b3f[tid];

    int nb = g_total >> 6;

    for (int bt = blockIdx.x; bt < nb; bt += gridDim.x) {
        __syncthreads();
        if (tid < 64) {
            unsigned e = g_wl[bt * 64 + tid];
            int seed = -1;
            if (e != 0xffffffffu) {
                seed = (int)(e >> 8);
                int gi = seed * UCAP + (int)(e & 255u);
                sX[tid] = g_uh[gi]; sX[64 + tid] = g_uy[gi]; sX[128 + tid] = g_uz[gi];
                sMask[tid] = (int)g_um[gi];
            } else {
                sX[tid] = 0.f; sX[64 + tid] = 0.f; sX[128 + tid] = 0.f; sMask[tid] = 0;
            }
            if ((tid & 3) == 0)
                sOB[tid >> 2] = (seed < 0) ? -1 : ((seed >> 10) * 1048576 + (seed & 1023) * 4);
        }
        __syncthreads();

        // ---- layer 1: 3 -> 64 ----
        {
            int o = tid >> 2, k0 = (tid & 3) << 4;
            float w0 = sW1[o * 3], w1 = sW1[o * 3 + 1], w2 = sW1[o * 3 + 2], bb = sB1[o];
#pragma unroll
            for (int j = 0; j < 16; j++) {
                int k = k0 + j;
                float v = bb + w0 * sX[k] + w1 * sX[64 + k] + w2 * sX[128 + k];
                sH1[o * 64 + k] = fmaxf(v, 0.f);
            }
        }
        __syncthreads();

        // ---- layer 2: 64 -> 128, f32x2, 4o x 8k per thread ----
        {
            int to = (tid >> 3) << 2, k0 = (tid & 7) << 3;
            unsigned long long acc[4][4];
#pragma unroll
            for (int i = 0; i < 4; i++)
#pragma unroll
                for (int q = 0; q < 4; q++) acc[i][q] = 0ull;
#pragma unroll 4
            for (int c4 = 0; c4 < 16; c4++) {
                int c = c4 << 2;
                ulonglong2 A[4][2];
#pragma unroll
                for (int cc = 0; cc < 4; cc++) {
                    A[cc][0] = *(const ulonglong2*)&sH1[(c + cc) * 64 + k0];
                    A[cc][1] = *(const ulonglong2*)&sH1[(c + cc) * 64 + k0 + 4];
                }
#pragma unroll
                for (int i = 0; i < 4; i++) {
                    float4 wv = *(const float4*)&sW2[(to + i) * 64 + c];
                    unsigned long long w0 = pack2(wv.x), w1 = pack2(wv.y),
                                       w2 = pack2(wv.z), w3 = pack2(wv.w);
                    acc[i][0] = fma2(w0, A[0][0].x, acc[i][0]);
                    acc[i][1] = fma2(w0, A[0][0].y, acc[i][1]);
                    acc[i][2] = fma2(w0, A[0][1].x, acc[i][2]);
                    acc[i][3] = fma2(w0, A[0][1].y, acc[i][3]);
                    acc[i][0] = fma2(w1, A[1][0].x, acc[i][0]);
                    acc[i][1] = fma2(w1, A[1][0].y, acc[i][1]);
                    acc[i][2] = fma2(w1, A[1][1].x, acc[i][2]);
                    acc[i][3] = fma2(w1, A[1][1].y, acc[i][3]);
                    acc[i][0] = fma2(w2, A[2][0].x, acc[i][0]);
                    acc[i][1] = fma2(w2, A[2][0].y, acc[i][1]);
                    acc[i][2] = fma2(w2, A[2][1].x, acc[i][2]);
                    acc[i][3] = fma2(w2, A[2][1].y, acc[i][3]);
                    acc[i][0] = fma2(w3, A[3][0].x, acc[i][0]);
                    acc[i][1] = fma2(w3, A[3][0].y, acc[i][1]);
                    acc[i][2] = fma2(w3, A[3][1].x, acc[i][2]);
                    acc[i][3] = fma2(w3, A[3][1].y, acc[i][3]);
                }
            }
#pragma unroll
            for (int i = 0; i < 4; i++) {
                float bb = sB2[to + i];
#pragma unroll
                for (int q = 0; q < 4; q++) {
                    float2 f = u2f(acc[i][q]);
                    float2 o2; o2.x = fmaxf(f.x + bb, 0.f); o2.y = fmaxf(f.y + bb, 0.f);
                    *(float2*)&sH2[(to + i) * 64 + k0 + 2 * q] = o2;
                }
            }
        }
        __syncthreads();

        // ---- layer 3: 128 -> 256, f32x2, 8o x 8k + depth-masked max + RED ---
        {
            int to = (tid >> 3) << 3, k0 = (tid & 7) << 3;
            unsigned long long acc[8][4];
#pragma unroll
            for (int i = 0; i < 8; i++)
#pragma unroll
                for (int q = 0; q < 4; q++) acc[i][q] = 0ull;
#pragma unroll 2
            for (int c4 = 0; c4 < 32; c4++) {
                int c = c4 << 2;
                ulonglong2 A[4][2];
#pragma unroll
                for (int cc = 0; cc < 4; cc++) {
                    A[cc][0] = *(const ulonglong2*)&sH2[(c + cc) * 64 + k0];
                    A[cc][1] = *(const ulonglong2*)&sH2[(c + cc) * 64 + k0 + 4];
                }
#pragma unroll
                for (int i = 0; i < 8; i++) {
                    float4 wv = *(const float4*)&sW3[(to + i) * 128 + c];
                    unsigned long long w0 = pack2(wv.x), w1 = pack2(wv.y),
                                       w2 = pack2(wv.z), w3 = pack2(wv.w);
                    acc[i][0] = fma2(w0, A[0][0].x, acc[i][0]);
                    acc[i][1] = fma2(w0, A[0][0].y, acc[i][1]);
                    acc[i][2] = fma2(w0, A[0][1].x, acc[i][2]);
                    acc[i][3] = fma2(w0, A[0][1].y, acc[i][3]);
                    acc[i][0] = fma2(w1, A[1][0].x, acc[i][0]);
                    acc[i][1] = fma2(w1, A[1][0].y, acc[i][1]);
                    acc[i][2] = fma2(w1, A[1][1].x, acc[i][2]);
                    acc[i][3] = fma2(w1, A[1][1].y, acc[i][3]);
                    acc[i][0] = fma2(w2, A[2][0].x, acc[i][0]);
                    acc[i][1] = fma2(w2, A[2][0].y, acc[i][1]);
                    acc[i][2] = fma2(w2, A[2][1].x, acc[i][2]);
                    acc[i][3] = fma2(w2, A[2][1].y, acc[i][3]);
                    acc[i][0] = fma2(w3, A[3][0].x, acc[i][0]);
                    acc[i][1] = fma2(w3, A[3][0].y, acc[i][1]);
                    acc[i][2] = fma2(w3, A[3][1].x, acc[i][2]);
                    acc[i][3] = fma2(w3, A[3][1].y, acc[i][3]);
                }
            }
            // epilogue: two 4-col units; per-unit depth-masked max + atomics
            float b3r[8];
#pragma unroll
            for (int i = 0; i < 8; i++) b3r[i] = sB3[to + i];
            int mk[8];
#pragma unroll
            for (int j = 0; j < 8; j++) mk[j] = sMask[k0 + j];
#pragma unroll
            for (int half = 0; half < 2; half++) {
                int ubH = mk[4 * half] | mk[4 * half + 1] | mk[4 * half + 2] | mk[4 * half + 3];
                int ob = sOB[(k0 >> 2) + half];
                if (ob < 0 || ubH == 0) continue;
                float vm[4][8];
#pragma unroll
                for (int d = 0; d < 4; d++)
#pragma unroll
                    for (int i = 0; i < 8; i++) vm[d][i] = 0.f;
#pragma unroll
                for (int qq = 0; qq < 2; qq++) {
                    int q = 2 * half + qq;
                    int m0 = mk[2 * q], m1 = mk[2 * q + 1];
#pragma unroll
                    for (int i = 0; i < 8; i++) {
                        float2 f = u2f(acc[i][q]);
                        float va = fmaxf(f.x + b3r[i], 0.f);
                        float vb = fmaxf(f.y + b3r[i], 0.f);
                        if (m0 & 1) vm[0][i] = fmaxf(vm[0][i], va);
                        if (m0 & 2) vm[1][i] = fmaxf(vm[1][i], va);
                        if (m0 & 4) vm[2][i] = fmaxf(vm[2][i], va);
                        if (m0 & 8) vm[3][i] = fmaxf(vm[3][i], va);
                        if (m1 & 1) vm[0][i] = fmaxf(vm[0][i], vb);
                        if (m1 & 2) vm[1][i] = fmaxf(vm[1][i], vb);
                        if (m1 & 4) vm[2][i] = fmaxf(vm[2][i], vb);
                        if (m1 & 8) vm[3][i] = fmaxf(vm[3][i], vb);
                    }
                }
#pragma unroll
                for (int d = 0; d < 4; d++) {
                    if ((ubH >> d) & 1) {
                        int* op = (int*)out + ob + d;
#pragma unroll
                        for (int i = 0; i < 8; i++)
                            atomicMax(op + (to + i) * 4096, __float_as_int(vm[d][i]));
                    }
                }
            }
        }
    }
}

// ---------------- launch ----------------------------------------------------
extern "C" void kernel_launch(void* const* d_in, const int* in_sizes, int n_in,
                              void* d_out, int out_size)
{
    const float* seed = (const float*)d_in[0];
    const float* pc   = (const float*)d_in[1];
    const float* vp   = (const float*)d_in[2];
    float* out = (float*)d_out;

    cudaFuncSetAttribute(mlp_kernel, cudaFuncAttributeMaxDynamicSharedMemorySize, SMEM2_BYTES);

    prep_kernel<<<512, 256>>>(pc,
        (const float*)d_in[3],  (const float*)d_in[4],  (const float*)d_in[5],
        (const float*)d_in[6],  (const float*)d_in[7],  (const float*)d_in[8],
        (const float*)d_in[9],  (const float*)d_in[10], (const float*)d_in[11],
        (const float*)d_in[12], (const float*)d_in[13], (const float*)d_in[14],
        (const float*)d_in[15], (const float*)d_in[16], (const float*)d_in[17],
        (const float*)d_in[18], (const float*)d_in[19], (const float*)d_in[20],
        out);
    group_kernel<<<NSEEDT, 128>>>(seed, vp);
    pack_kernel<<<1, 1024>>>();
    mlp_kernel<<<152, 256, SMEM2_BYTES>>>(out);
}

// round 15
// speedup vs baseline: 2.3896x; 1.0024x over previous
#include <cuda_runtime.h>

#define NPTS   16384
#define NBATCH 2
#define NSEED  1024
#define NSEEDT (NBATCH*NSEED)          // 2048
#define OUTSZ  (NBATCH*256*NSEED*4)
#define UCAP   256                     // max union samples per seed (4*64)

// ---------------- scratch (__device__ globals; no allocation allowed) -------
__device__ float    g_px[NBATCH][NPTS];
__device__ float    g_py[NBATCH][NPTS];
__device__ float    g_pz[NBATCH][NPTS];
__device__ float    g_uh[NSEEDT * UCAP];
__device__ float    g_uy[NSEEDT * UCAP];
__device__ float    g_uz[NSEEDT * UCAP];
__device__ unsigned char g_um[NSEEDT * UCAP];   // 4-bit depth membership mask
__device__ int      g_ucnt[NSEEDT];
__device__ unsigned g_wl[NSEEDT * UCAP + 64];   // worklist: seed<<8 | idx
__device__ int      g_total;
__device__ float    g_w1f[192],   g_b1f[64];
__device__ float    g_w2f[8192],  g_b2f[128];
__device__ float    g_w3f[32768], g_b3f[256];

// ---------------- f32x2 helpers (FFMA2 path: 2x fp32 FMA throughput) --------
__device__ __forceinline__ unsigned long long fma2(unsigned long long a,
                                                   unsigned long long b,
                                                   unsigned long long c) {
    unsigned long long d;
    asm("fma.rn.f32x2 %0, %1, %2, %3;" : "=l"(d) : "l"(a), "l"(b), "l"(c));
    return d;
}
__device__ __forceinline__ unsigned long long pack2(float x) {
    unsigned long long r;
    asm("mov.b64 %0, {%1, %1};" : "=l"(r) : "f"(x));
    return r;
}
__device__ __forceinline__ float2 u2f(unsigned long long v) {
    float2 f;
    asm("mov.b64 {%0, %1}, %2;" : "=f"(f.x), "=f"(f.y) : "l"(v));
    return f;
}

// ---------------- kernel 0: fold BN into weights, SoA transpose, zero out ---
__global__ void prep_kernel(
    const float* __restrict__ pc,
    const float* __restrict__ w1, const float* __restrict__ b1, const float* __restrict__ ga1,
    const float* __restrict__ be1, const float* __restrict__ m1, const float* __restrict__ v1,
    const float* __restrict__ w2, const float* __restrict__ b2, const float* __restrict__ ga2,
    const float* __restrict__ be2, const float* __restrict__ m2, const float* __restrict__ v2,
    const float* __restrict__ w3, const float* __restrict__ b3, const float* __restrict__ ga3,
    const float* __restrict__ be3, const float* __restrict__ m3, const float* __restrict__ v3,
    float* __restrict__ out)
{
    int tid = blockIdx.x * blockDim.x + threadIdx.x;
    int stride = gridDim.x * blockDim.x;
    for (int i = tid; i < 192; i += stride)   { int o = i / 3;  g_w1f[i] = w1[i] * (ga1[o] * rsqrtf(v1[o] + 1e-5f)); }
    for (int i = tid; i < 64; i += stride)    { float s = ga1[i] * rsqrtf(v1[i] + 1e-5f); g_b1f[i] = (b1[i] - m1[i]) * s + be1[i]; }
    for (int i = tid; i < 8192; i += stride)  { int o = i >> 6; g_w2f[i] = w2[i] * (ga2[o] * rsqrtf(v2[o] + 1e-5f)); }
    for (int i = tid; i < 128; i += stride)   { float s = ga2[i] * rsqrtf(v2[i] + 1e-5f); g_b2f[i] = (b2[i] - m2[i]) * s + be2[i]; }
    for (int i = tid; i < 32768; i += stride) { int o = i >> 7; g_w3f[i] = w3[i] * (ga3[o] * rsqrtf(v3[o] + 1e-5f)); }
    for (int i = tid; i < 256; i += stride)   { float s = ga3[i] * rsqrtf(v3[i] + 1e-5f); g_b3f[i] = (b3[i] - m3[i]) * s + be3[i]; }
    for (int i = tid; i < NBATCH * NPTS; i += stride) {
        int b = i >> 14, n = i & (NPTS - 1);
        const float* p = pc + (size_t)i * 3;
        g_px[b][n] = p[0]; g_py[b][n] = p[1]; g_pz[b][n] = p[2];
    }
    for (int i = tid; i < OUTSZ; i += stride) out[i] = 0.0f;
}

// ---------------- kernel 1: 8 seeds/block, smem point tiling ----------------
// Each block stages 2048-pt chunks into smem (loaded once, used by 8 warps);
// each warp scans its seed IN ORDER with global counters -> exact reference
// selection semantics. Block-wide early exit once all warps hit their caps.
#define CHSZ 2048
__global__ void __launch_bounds__(256) group_kernel(
    const float* __restrict__ seed_xyz, const float* __restrict__ vp_rot)
{
    __shared__ float chx[CHSZ], chy[CHSZ], chz[CHSZ];
    __shared__ int sDone;
    int tid = threadIdx.x, lane = tid & 31, w = tid >> 5;
    int seed = blockIdx.x * 8 + w;                 // blocks batch-aligned (1024%8==0)
    int b = seed >> 10;

    const float* sp = seed_xyz + (size_t)seed * 3;
    float sx = sp[0], sy = sp[1], sz = sp[2];
    const float* R = vp_rot + (size_t)seed * 9;
    float r00 = R[0], r01 = R[1], r02 = R[2];
    float r10 = R[3], r11 = R[4], r12 = R[5];
    float r20 = R[6], r21 = R[7], r22 = R[8];

    const float* __restrict__ px = g_px[b];
    const float* __restrict__ py = g_py[b];
    const float* __restrict__ pz = g_pz[b];

    if (tid == 0) sDone = 0;
    int c0 = 0, c1 = 0, c2 = 0, c3 = 0, u = 0;
    bool done = false;
    unsigned lm = (1u << lane) - 1u;
    int gbase = seed * UCAP;

    for (int base = 0; base < NPTS; base += CHSZ) {
        __syncthreads();                 // guards chunk reuse AND sDone visibility
        if (sDone == 8) break;
        for (int i = tid; i < CHSZ; i += 256) {
            chx[i] = px[base + i]; chy[i] = py[base + i]; chz[i] = pz[base + i];
        }
        __syncthreads();
        if (done) continue;

        float nx = chx[lane], ny = chy[lane], nz = chz[lane];
        for (int it = 0; it < CHSZ; it += 32) {
            float X = nx, Y = ny, Z = nz;
            int ip = (it + 32 < CHSZ) ? (it + 32 + lane) : lane;
            nx = chx[ip]; ny = chy[ip]; nz = chz[ip];   // prefetch breaks LDS chain

            float dx = X - sx, dy = Y - sy, dz = Z - sz;
            float h  = dx * r00 + dy * r10 + dz * r20;
            float yy = dx * r01 + dy * r11 + dz * r21;
            float zz = dx * r02 + dy * r12 + dz * r22;
            bool bs = (yy * yy + zz * zz < 0.0025f) && (h > -0.02f) && (h < 0.04f);
            unsigned m3 = __ballot_sync(0xffffffffu, bs);
            if (!m3) continue;
            unsigned m0 = __ballot_sync(0xffffffffu, bs && h < 0.01f);
            unsigned m1 = __ballot_sync(0xffffffffu, bs && h < 0.02f);
            unsigned m2 = __ballot_sync(0xffffffffu, bs && h < 0.03f);
            int bits = 0;
            if (bs) {
                if (h < 0.01f && c0 + __popc(m0 & lm) < 64) bits |= 1;
                if (h < 0.02f && c1 + __popc(m1 & lm) < 64) bits |= 2;
                if (h < 0.03f && c2 + __popc(m2 & lm) < 64) bits |= 4;
                if (            c3 + __popc(m3 & lm) < 64) bits |= 8;
            }
            unsigned be = __ballot_sync(0xffffffffu, bits != 0);
            if (bits) {
                int s = gbase + u + __popc(be & lm);
                g_uh[s] = h; g_uy[s] = yy; g_uz[s] = zz;
                g_um[s] = (unsigned char)bits;
            }
            u  += __popc(be);
            c0 += __popc(m0); c1 += __popc(m1); c2 += __popc(m2); c3 += __popc(m3);
            if (c0 >= 64) {                      // nested masks: all caps hit
                done = true;
                if (lane == 0) atomicAdd(&sDone, 1);
                break;
            }
        }
    }

    // fallback: empty depths use d_rot of point 0 (reference pads with idx 0)
    int ebits = (c0 == 0 ? 1 : 0) | (c1 == 0 ? 2 : 0) | (c2 == 0 ? 4 : 0) | (c3 == 0 ? 8 : 0);
    if (ebits) {
        if (lane == 0) {
            float fdx = px[0] - sx, fdy = py[0] - sy, fdz = pz[0] - sz;
            int s = gbase + u;
            g_uh[s] = fdx * r00 + fdy * r10 + fdz * r20;
            g_uy[s] = fdx * r01 + fdy * r11 + fdz * r21;
            g_uz[s] = fdx * r02 + fdy * r12 + fdz * r22;
            g_um[s] = (unsigned char)ebits;
        }
        u++;
    }
    if (lane == 0) g_ucnt[seed] = u;
}

// ---------------- kernel 1.5: pack worklist, seeds padded to 4-col units ----
__global__ void __launch_bounds__(1024) pack_kernel()
{
    __shared__ int soff[NSEEDT];
    __shared__ int wsum[32];
    int tid = threadIdx.x, lane = tid & 31, w = tid >> 5;

    int cA = (g_ucnt[2 * tid]     + 3) & ~3;
    int cB = (g_ucnt[2 * tid + 1] + 3) & ~3;
    int s = cA + cB;
    int v = s;
#pragma unroll
    for (int o = 1; o < 32; o <<= 1) { int t = __shfl_up_sync(0xffffffffu, v, o); if (lane >= o) v += t; }
    if (lane == 31) wsum[w] = v;
    __syncthreads();
    if (tid < 32) {
        int t = wsum[tid];
#pragma unroll
        for (int o = 1; o < 32; o <<= 1) { int x = __shfl_up_sync(0xffffffffu, t, o); if (tid >= o) t += x; }
        wsum[tid] = t;
    }
    __syncthreads();
    int excl = v - s + (w ? wsum[w - 1] : 0);
    soff[2 * tid] = excl; soff[2 * tid + 1] = excl + cA;
    __syncthreads();

    int total = wsum[31];
    for (int seed = tid; seed < NSEEDT; seed += 1024) {
        int basep = soff[seed], cnt = g_ucnt[seed], pc = (cnt + 3) & ~3;
        for (int p = 0; p < pc; p++) {
            int idx = p < cnt ? p : cnt - 1;   // dup pad == identity for max
            g_wl[basep + p] = (unsigned)((seed << 8) | idx);
        }
    }
    int tot64 = (total + 63) & ~63;
    for (int i = total + tid; i < tot64; i += 1024) g_wl[i] = 0xffffffffu;
    if (tid == 0) g_total = tot64;
}

// ---------------- kernel 2: persistent fused MLP (f32x2) --------------------
#define SMEM2_FLOATS (8192 + 32768 + 192 + 64 + 128 + 256 + 192 + 4096 + 8192 + 64 + 16)
#define SMEM2_BYTES  (SMEM2_FLOATS * 4)

__global__ void __launch_bounds__(256, 1) mlp_kernel(float* __restrict__ out)
{
    extern __shared__ float sm[];
    float* sW2 = sm;                  // 8192
    float* sW3 = sW2 + 8192;          // 32768
    float* sW1 = sW3 + 32768;         // 192
    float* sB1 = sW1 + 192;           // 64
    float* sB2 = sB1 + 64;            // 128
    float* sB3 = sB2 + 128;           // 256
    float* sX  = sB3 + 256;           // 192  (3 x 64)
    float* sH1 = sX + 192;            // 4096 (64 x 64)
    float* sH2 = sH1 + 4096;          // 8192 (128 x 64)
    int*  sMask = (int*)(sH2 + 8192); // 64
    int*  sOB   = sMask + 64;         // 16 (per 4-col unit: output base or -1)

    int tid = threadIdx.x;
    for (int i = tid; i < 8192; i += 256)  sW2[i] = g_w2f[i];
    for (int i = tid; i < 32768; i += 256) sW3[i] = g_w3f[i];
    if (tid < 192) sW1[tid] = g_w1f[tid];
    if (tid < 64)  sB1[tid] = g_b1f[tid];
    if (tid < 128) sB2[tid] = g_b2f[tid];
    sB3[tid] = g_b3f[tid];

    int nb = g_total >> 6;

    for (int bt = blockIdx.x; bt < nb; bt += gridDim.x) {
        __syncthreads();
        if (tid < 64) {
            unsigned e = g_wl[bt * 64 + tid];
            int seed = -1;
            if (e != 0xffffffffu) {
                seed = (int)(e >> 8);
                int gi = seed * UCAP + (int)(e & 255u);
                sX[tid] = g_uh[gi]; sX[64 + tid] = g_uy[gi]; sX[128 + tid] = g_uz[gi];
                sMask[tid] = (int)g_um[gi];
            } else {
                sX[tid] = 0.f; sX[64 + tid] = 0.f; sX[128 + tid] = 0.f; sMask[tid] = 0;
            }
            if ((tid & 3) == 0)
                sOB[tid >> 2] = (seed < 0) ? -1 : ((seed >> 10) * 1048576 + (seed & 1023) * 4);
        }
        __syncthreads();

        // ---- layer 1: 3 -> 64 ----
        {
            int o = tid >> 2, k0 = (tid & 3) << 4;
            float w0 = sW1[o * 3], w1 = sW1[o * 3 + 1], w2 = sW1[o * 3 + 2], bb = sB1[o];
#pragma unroll
            for (int j = 0; j < 16; j++) {
                int k = k0 + j;
                float v = bb + w0 * sX[k] + w1 * sX[64 + k] + w2 * sX[128 + k];
                sH1[o * 64 + k] = fmaxf(v, 0.f);
            }
        }
        __syncthreads();

        // ---- layer 2: 64 -> 128, f32x2, 4o x 8k per thread ----
        {
            int to = (tid >> 3) << 2, k0 = (tid & 7) << 3;
            unsigned long long acc[4][4];
#pragma unroll
            for (int i = 0; i < 4; i++)
#pragma unroll
                for (int q = 0; q < 4; q++) acc[i][q] = 0ull;
#pragma unroll 4
            for (int c4 = 0; c4 < 16; c4++) {
                int c = c4 << 2;
                ulonglong2 A[4][2];
#pragma unroll
                for (int cc = 0; cc < 4; cc++) {
                    A[cc][0] = *(const ulonglong2*)&sH1[(c + cc) * 64 + k0];
                    A[cc][1] = *(const ulonglong2*)&sH1[(c + cc) * 64 + k0 + 4];
                }
#pragma unroll
                for (int i = 0; i < 4; i++) {
                    float4 wv = *(const float4*)&sW2[(to + i) * 64 + c];
                    unsigned long long w0 = pack2(wv.x), w1 = pack2(wv.y),
                                       w2 = pack2(wv.z), w3 = pack2(wv.w);
                    acc[i][0] = fma2(w0, A[0][0].x, acc[i][0]);
                    acc[i][1] = fma2(w0, A[0][0].y, acc[i][1]);
                    acc[i][2] = fma2(w0, A[0][1].x, acc[i][2]);
                    acc[i][3] = fma2(w0, A[0][1].y, acc[i][3]);
                    acc[i][0] = fma2(w1, A[1][0].x, acc[i][0]);
                    acc[i][1] = fma2(w1, A[1][0].y, acc[i][1]);
                    acc[i][2] = fma2(w1, A[1][1].x, acc[i][2]);
                    acc[i][3] = fma2(w1, A[1][1].y, acc[i][3]);
                    acc[i][0] = fma2(w2, A[2][0].x, acc[i][0]);
                    acc[i][1] = fma2(w2, A[2][0].y, acc[i][1]);
                    acc[i][2] = fma2(w2, A[2][1].x, acc[i][2]);
                    acc[i][3] = fma2(w2, A[2][1].y, acc[i][3]);
                    acc[i][0] = fma2(w3, A[3][0].x, acc[i][0]);
                    acc[i][1] = fma2(w3, A[3][0].y, acc[i][1]);
                    acc[i][2] = fma2(w3, A[3][1].x, acc[i][2]);
                    acc[i][3] = fma2(w3, A[3][1].y, acc[i][3]);
                }
            }
#pragma unroll
            for (int i = 0; i < 4; i++) {
                float bb = sB2[to + i];
#pragma unroll
                for (int q = 0; q < 4; q++) {
                    float2 f = u2f(acc[i][q]);
                    float2 o2; o2.x = fmaxf(f.x + bb, 0.f); o2.y = fmaxf(f.y + bb, 0.f);
                    *(float2*)&sH2[(to + i) * 64 + k0 + 2 * q] = o2;
                }
            }
        }
        __syncthreads();

        // ---- layer 3: 128 -> 256, f32x2, 8o x 8k + depth-masked max + RED ---
        {
            int to = (tid >> 3) << 3, k0 = (tid & 7) << 3;
            unsigned long long acc[8][4];
#pragma unroll
            for (int i = 0; i < 8; i++)
#pragma unroll
                for (int q = 0; q < 4; q++) acc[i][q] = 0ull;
#pragma unroll 2
            for (int c4 = 0; c4 < 32; c4++) {
                int c = c4 << 2;
                ulonglong2 A[4][2];
#pragma unroll
                for (int cc = 0; cc < 4; cc++) {
                    A[cc][0] = *(const ulonglong2*)&sH2[(c + cc) * 64 + k0];
                    A[cc][1] = *(const ulonglong2*)&sH2[(c + cc) * 64 + k0 + 4];
                }
#pragma unroll
                for (int i = 0; i < 8; i++) {
                    float4 wv = *(const float4*)&sW3[(to + i) * 128 + c];
                    unsigned long long w0 = pack2(wv.x), w1 = pack2(wv.y),
                                       w2 = pack2(wv.z), w3 = pack2(wv.w);
                    acc[i][0] = fma2(w0, A[0][0].x, acc[i][0]);
                    acc[i][1] = fma2(w0, A[0][0].y, acc[i][1]);
                    acc[i][2] = fma2(w0, A[0][1].x, acc[i][2]);
                    acc[i][3] = fma2(w0, A[0][1].y, acc[i][3]);
                    acc[i][0] = fma2(w1, A[1][0].x, acc[i][0]);
                    acc[i][1] = fma2(w1, A[1][0].y, acc[i][1]);
                    acc[i][2] = fma2(w1, A[1][1].x, acc[i][2]);
                    acc[i][3] = fma2(w1, A[1][1].y, acc[i][3]);
                    acc[i][0] = fma2(w2, A[2][0].x, acc[i][0]);
                    acc[i][1] = fma2(w2, A[2][0].y, acc[i][1]);
                    acc[i][2] = fma2(w2, A[2][1].x, acc[i][2]);
                    acc[i][3] = fma2(w2, A[2][1].y, acc[i][3]);
                    acc[i][0] = fma2(w3, A[3][0].x, acc[i][0]);
                    acc[i][1] = fma2(w3, A[3][0].y, acc[i][1]);
                    acc[i][2] = fma2(w3, A[3][1].x, acc[i][2]);
                    acc[i][3] = fma2(w3, A[3][1].y, acc[i][3]);
                }
            }
            // epilogue: two 4-col units; per-unit depth-masked max + atomics
            float b3r[8];
#pragma unroll
            for (int i = 0; i < 8; i++) b3r[i] = sB3[to + i];
            int mk[8];
#pragma unroll
            for (int j = 0; j < 8; j++) mk[j] = sMask[k0 + j];
#pragma unroll
            for (int half = 0; half < 2; half++) {
                int ubH = mk[4 * half] | mk[4 * half + 1] | mk[4 * half + 2] | mk[4 * half + 3];
                int ob = sOB[(k0 >> 2) + half];
                if (ob < 0 || ubH == 0) continue;
                float vm[4][8];
#pragma unroll
                for (int d = 0; d < 4; d++)
#pragma unroll
                    for (int i = 0; i < 8; i++) vm[d][i] = 0.f;
#pragma unroll
                for (int qq = 0; qq < 2; qq++) {
                    int q = 2 * half + qq;
                    int m0 = mk[2 * q], m1 = mk[2 * q + 1];
#pragma unroll
                    for (int i = 0; i < 8; i++) {
                        float2 f = u2f(acc[i][q]);
                        float va = fmaxf(f.x + b3r[i], 0.f);
                        float vb = fmaxf(f.y + b3r[i], 0.f);
                        if (m0 & 1) vm[0][i] = fmaxf(vm[0][i], va);
                        if (m0 & 2) vm[1][i] = fmaxf(vm[1][i], va);
                        if (m0 & 4) vm[2][i] = fmaxf(vm[2][i], va);
                        if (m0 & 8) vm[3][i] = fmaxf(vm[3][i], va);
                        if (m1 & 1) vm[0][i] = fmaxf(vm[0][i], vb);
                        if (m1 & 2) vm[1][i] = fmaxf(vm[1][i], vb);
                        if (m1 & 4) vm[2][i] = fmaxf(vm[2][i], vb);
                        if (m1 & 8) vm[3][i] = fmaxf(vm[3][i], vb);
                    }
                }
#pragma unroll
                for (int d = 0; d < 4; d++) {
                    if ((ubH >> d) & 1) {
                        int* op = (int*)out + ob + d;
#pragma unroll
                        for (int i = 0; i < 8; i++)
                            atomicMax(op + (to + i) * 4096, __float_as_int(vm[d][i]));
                    }
                }
            }
        }
    }
}

// ---------------- launch ----------------------------------------------------
extern "C" void kernel_launch(void* const* d_in, const int* in_sizes, int n_in,
                              void* d_out, int out_size)
{
    const float* seed = (const float*)d_in[0];
    const float* pc   = (const float*)d_in[1];
    const float* vp   = (const float*)d_in[2];
    float* out = (float*)d_out;

    cudaFuncSetAttribute(mlp_kernel, cudaFuncAttributeMaxDynamicSharedMemorySize, SMEM2_BYTES);

    prep_kernel<<<512, 256>>>(pc,
        (const float*)d_in[3],  (const float*)d_in[4],  (const float*)d_in[5],
        (const float*)d_in[6],  (const float*)d_in[7],  (const float*)d_in[8],
        (const float*)d_in[9],  (const float*)d_in[10], (const float*)d_in[11],
        (const float*)d_in[12], (const float*)d_in[13], (const float*)d_in[14],
        (const float*)d_in[15], (const float*)d_in[16], (const float*)d_in[17],
        (const float*)d_in[18], (const float*)d_in[19], (const float*)d_in[20],
        out);
    group_kernel<<<NSEEDT / 8, 256>>>(seed, vp);
    pack_kernel<<<1, 1024>>>();
    mlp_kernel<<<152, 256, SMEM2_BYTES>>>(out);
}